// round 15
// baseline (speedup 1.0000x reference)
#include <cuda_runtime.h>
#include <cuda_fp16.h>
#include <math.h>
#include <stdint.h>

#define Bb 8
#define Tt 1024
#define Ee 1024
#define Hh 16
#define Dh 64
#define Mm (Bb*Tt)   // 8192

// Scratch (allocation-free rule: __device__ globals), all fp16 operands
__device__ __half g_Qh[Bb*Hh*Tt*Dh];
__device__ __half g_Kh[Bb*Hh*Tt*Dh];
__device__ __half g_Vh[Bb*Hh*Tt*Dh];
__device__ __half g_Hid[Mm*Ee];
__device__ __half g_Xh[Mm*Ee];
__device__ __half g_Wth[3*Ee*Ee];    // transposed [3072][1024]
__device__ __half g_Wph[Ee*Ee];      // Wp (already [n][k])

// ============================ helpers ============================
__device__ __forceinline__ uint32_t smem_u32(const void* p) {
    uint32_t a;
    asm("{ .reg .u64 t; cvta.to.shared.u64 t, %1; cvt.u32.u64 %0, t; }"
        : "=r"(a) : "l"(p));
    return a;
}
__device__ __forceinline__ uint32_t h2u(__half2 h) {
    return *reinterpret_cast<uint32_t*>(&h);
}
#define LDSM_X4(r0, r1, r2, r3, addr) \
    asm volatile("ldmatrix.sync.aligned.m8n8.x4.shared.b16 {%0,%1,%2,%3}, [%4];" \
                 : "=r"(r0), "=r"(r1), "=r"(r2), "=r"(r3) : "r"(addr))
#define LDSM_X4_T(r0, r1, r2, r3, addr) \
    asm volatile("ldmatrix.sync.aligned.m8n8.x4.trans.shared.b16 {%0,%1,%2,%3}, [%4];" \
                 : "=r"(r0), "=r"(r1), "=r"(r2), "=r"(r3) : "r"(addr))
#define CP16(dst, src) \
    asm volatile("cp.async.cg.shared.global [%0], [%1], 16;" \
                 :: "r"(dst), "l"(src) : "memory")
#define CP_COMMIT() asm volatile("cp.async.commit_group;" ::: "memory")
#define CP_WAIT1()  asm volatile("cp.async.wait_group 1;" ::: "memory")
#define CP_WAIT0()  asm volatile("cp.async.wait_group 0;" ::: "memory")

__device__ __forceinline__ void mma_f16(float* d, const uint32_t* a,
                                        uint32_t b0, uint32_t b1) {
    asm volatile(
        "mma.sync.aligned.m16n8k16.row.col.f32.f16.f16.f32 "
        "{%0,%1,%2,%3}, {%4,%5,%6,%7}, {%8,%9}, {%0,%1,%2,%3};"
        : "+f"(d[0]), "+f"(d[1]), "+f"(d[2]), "+f"(d[3])
        : "r"(a[0]), "r"(a[1]), "r"(a[2]), "r"(a[3]), "r"(b0), "r"(b1));
}

// ---------------------------------------------------------------------------
// Prep kernels: fp32 -> fp16 conversions
// ---------------------------------------------------------------------------
__global__ __launch_bounds__(256) void prep_half_kernel(
    const float* __restrict__ src, __half* __restrict__ dst)
{
    const size_t i = ((size_t)blockIdx.x * 256 + threadIdx.x) * 4;
    float4 v = *(const float4*)(src + i);
    __half2 h0 = __floats2half2_rn(v.x, v.y);
    __half2 h1 = __floats2half2_rn(v.z, v.w);
    *(uint2*)(dst + i) = make_uint2(h2u(h0), h2u(h1));
}

// W[h][k][d] -> Wth[which*1024 + h*64 + d][k], fp16
__global__ __launch_bounds__(256) void prep_wth_kernel(
    const float* __restrict__ Wq, const float* __restrict__ Wk,
    const float* __restrict__ Wv)
{
    __shared__ float tile[32][33];
    const int which = blockIdx.z >> 4;
    const int h = blockIdx.z & 15;
    const float* Ws = (which == 0) ? Wq : ((which == 1) ? Wk : Wv);
    const int k0 = blockIdx.x * 32;
    const int d0 = blockIdx.y * 32;
    const int tx = threadIdx.x & 31, ty = threadIdx.x >> 5;

#pragma unroll
    for (int j = 0; j < 4; ++j) {
        const int kk = ty + j * 8;
        tile[kk][tx] = Ws[(size_t)h * (Ee * Dh) + (size_t)(k0 + kk) * Dh + d0 + tx];
    }
    __syncthreads();
#pragma unroll
    for (int j = 0; j < 4; ++j) {
        const int dd = ty + j * 8;
        const int n = h * 64 + d0 + dd;
        g_Wth[(size_t)which * (Ee * Ee) + (size_t)n * Ee + k0 + tx] =
            __float2half_rn(tile[tx][dd]);
    }
}

// ---------------------------------------------------------------------------
// QKV GEMM (R14-proven). Warp tile 64x32, K-chunk 64, 4-stage cp.async ring,
// cross-chunk register fragment prefetch. 12 warps (CTA 128x192).
// ---------------------------------------------------------------------------
#define GPITCH 72                         // halves per row
#define GROWB (GPITCH*2)                  // 144 bytes
#define GABYTES (128*GROWB)               // 18432

__global__ __launch_bounds__(384, 1) void qkv_mma_kernel()
{
    constexpr int WN = 6;
    constexpr int BB = WN * 32 * GROWB;
    constexpr int STAGE = GABYTES + BB;

    const int n0g = blockIdx.x * 192;
    const __half* A = g_Xh;
    const __half* Brows = g_Wth + (size_t)n0g * Ee;
    const int m0 = blockIdx.y * 128;

    extern __shared__ uint32_t dsm[];
    const uint32_t sb = smem_u32(dsm);

    const int tid = threadIdx.x;
    const int lane = tid & 31;
    const int wid = tid >> 5;
    const int warp_m = wid & 1;
    const int warp_n = wid >> 1;

    float acc[4][4][4] = {};

    const uint32_t a_frag0 = sb +
        (warp_m * 64 + (lane & 15)) * GROWB + (lane >> 4) * 16;
    const uint32_t b_frag0 = sb + GABYTES +
        (warp_n * 32 + (lane & 7) + ((lane >> 4) << 3)) * GROWB
        + ((lane >> 3) & 1) * 16;

    const int c_row = tid >> 1;
    const int c_col = (tid & 1) * 32;

    const __half* asrc0 = A + (size_t)(m0 + (c_row & 127)) * Ee + c_col;
    const __half* bsrc0 = Brows + (size_t)c_row * Ee + c_col;
    const uint32_t adst0 = sb + (c_row & 127) * GROWB + c_col * 2;
    const uint32_t bdst0 = sb + GABYTES + c_row * GROWB + c_col * 2;

    auto copy_chunk = [&](int c, int stg) {
        const uint32_t off = (uint32_t)stg * STAGE;
        const int k0 = c * 64;
        if (tid < 256) {
#pragma unroll
            for (int j = 0; j < 4; ++j)
                CP16(adst0 + off + 16 * j, asrc0 + k0 + 8 * j);
        }
#pragma unroll
        for (int j = 0; j < 4; ++j)
            CP16(bdst0 + off + 16 * j, bsrc0 + k0 + 8 * j);
    };

    copy_chunk(0, 0); CP_COMMIT();
    copy_chunk(1, 1); CP_COMMIT();
    copy_chunk(2, 2); CP_COMMIT();

    uint32_t af[2][4][4], bf[2][2][4];

    for (int c = 0; c < 16; ++c) {
        if (c < 14) CP_WAIT1(); else CP_WAIT0();
        __syncthreads();
        if (c < 13) { copy_chunk(c + 3, (c + 3) & 3); CP_COMMIT(); }

        const uint32_t af_b = a_frag0 + (uint32_t)(c & 3) * STAGE;
        const uint32_t bf_b = b_frag0 + (uint32_t)(c & 3) * STAGE;
        const uint32_t af_n = a_frag0 + (uint32_t)((c + 1) & 3) * STAGE;
        const uint32_t bf_n = b_frag0 + (uint32_t)((c + 1) & 3) * STAGE;

        if (c == 0) {
#pragma unroll
            for (int mt = 0; mt < 4; ++mt)
                LDSM_X4(af[0][mt][0], af[0][mt][1], af[0][mt][2], af[0][mt][3],
                        af_b + (uint32_t)(mt * 16 * GROWB));
#pragma unroll
            for (int nb2 = 0; nb2 < 2; ++nb2)
                LDSM_X4(bf[0][nb2][0], bf[0][nb2][1], bf[0][nb2][2], bf[0][nb2][3],
                        bf_b + (uint32_t)(nb2 * 16 * GROWB));
        }

#pragma unroll
        for (int ks = 0; ks < 4; ++ks) {
            const int cur = ks & 1, nxt = cur ^ 1;
            if (ks < 3) {
#pragma unroll
                for (int mt = 0; mt < 4; ++mt)
                    LDSM_X4(af[nxt][mt][0], af[nxt][mt][1],
                            af[nxt][mt][2], af[nxt][mt][3],
                            af_b + (uint32_t)(mt * 16 * GROWB + (ks + 1) * 32));
#pragma unroll
                for (int nb2 = 0; nb2 < 2; ++nb2)
                    LDSM_X4(bf[nxt][nb2][0], bf[nxt][nb2][1],
                            bf[nxt][nb2][2], bf[nxt][nb2][3],
                            bf_b + (uint32_t)(nb2 * 16 * GROWB + (ks + 1) * 32));
            } else if (c < 15) {
#pragma unroll
                for (int mt = 0; mt < 4; ++mt)
                    LDSM_X4(af[nxt][mt][0], af[nxt][mt][1],
                            af[nxt][mt][2], af[nxt][mt][3],
                            af_n + (uint32_t)(mt * 16 * GROWB));
#pragma unroll
                for (int nb2 = 0; nb2 < 2; ++nb2)
                    LDSM_X4(bf[nxt][nb2][0], bf[nxt][nb2][1],
                            bf[nxt][nb2][2], bf[nxt][nb2][3],
                            bf_n + (uint32_t)(nb2 * 16 * GROWB));
            }
#pragma unroll
            for (int mt = 0; mt < 4; ++mt)
#pragma unroll
                for (int nt = 0; nt < 4; ++nt)
                    mma_f16(acc[mt][nt], af[cur][mt],
                            bf[cur][nt >> 1][(nt & 1) * 2],
                            bf[cur][nt >> 1][(nt & 1) * 2 + 1]);
        }
    }

    const int r_base = m0 + warp_m * 64 + (lane >> 2);
    const int c_base = n0g + warp_n * 32 + (lane & 3) * 2;
#pragma unroll
    for (int mt = 0; mt < 4; ++mt) {
#pragma unroll
        for (int nt = 0; nt < 4; ++nt) {
            const int row = r_base + mt * 16;
            const int colg = c_base + nt * 8;
            const int which = colg >> 10;
            __half* outp = (which == 0) ? g_Qh : ((which == 1) ? g_Kh : g_Vh);
            const int col = colg & 1023;
            const int h = col >> 6, d = col & 63;
            const int b1_ = row >> 10, t1 = row & 1023;
            const int b2_ = (row + 8) >> 10, t2 = (row + 8) & 1023;
            __half2 lo = __floats2half2_rn(acc[mt][nt][0], acc[mt][nt][1]);
            __half2 hi = __floats2half2_rn(acc[mt][nt][2], acc[mt][nt][3]);
            *(__half2*)(outp + (((size_t)(b1_ * Hh + h)) * Tt + t1) * Dh + d) = lo;
            *(__half2*)(outp + (((size_t)(b2_ * Hh + h)) * Tt + t2) * Dh + d) = hi;
        }
    }
}

#define QKV_SMEM (4*(GABYTES + 6*32*GROWB))      // 184320

// ---------------------------------------------------------------------------
// PROJ GEMM — EXPERIMENT: warp tile 64x64, single-buffered fragments.
// CTA 128x256, 8 warps (2m x 4n), K-chunk 64, 3-stage cp.async.
// Per ks: 4 LDSM A, 2 LDSM B-half0, 16 MMA, 2 LDSM B-half1 (reuse), 16 MMA.
// acc 128 + A 16 + B 8 + addr ~ 170 regs target (NO double buffering).
// ---------------------------------------------------------------------------
#define PABYTES (128*GROWB)               // 18432
#define PBBYTES (256*GROWB)               // 36864
#define PSTAGE (PABYTES+PBBYTES)          // 55296
#define PROJ_SMEM (3*PSTAGE)              // 165888

__global__ __launch_bounds__(256, 1) void proj_mma_kernel(
    const float* __restrict__ bp, float* __restrict__ out)
{
    extern __shared__ uint32_t dsm[];
    const uint32_t sb = smem_u32(dsm);

    const int tid = threadIdx.x;
    const int lane = tid & 31;
    const int wid = tid >> 5;
    const int warp_m = wid & 1;    // 2 x 64 rows
    const int warp_n = wid >> 1;   // 4 x 64 cols

    const int m0 = blockIdx.y * 128;
    const int n0 = blockIdx.x * 256;
    const __half* Brows = g_Wph + (size_t)n0 * Ee;

    float acc[4][8][4] = {};       // 128 regs

    const uint32_t a_frag0 = sb +
        (warp_m * 64 + (lane & 15)) * GROWB + (lane >> 4) * 16;
    const uint32_t b_frag0 = sb + PABYTES +
        (warp_n * 64 + (lane & 7) + ((lane >> 4) << 3)) * GROWB
        + ((lane >> 3) & 1) * 16;

    // cp.async: A 128 rows 2 thr/row (4 segs), B 256 rows 1 thr/row (8 segs)
    const __half* asrc0 = g_Hid + (size_t)(m0 + (tid >> 1)) * Ee + (tid & 1) * 32;
    const __half* bsrc0 = Brows + (size_t)tid * Ee;
    const uint32_t adst0 = sb + (tid >> 1) * GROWB + (tid & 1) * 64;
    const uint32_t bdst0 = sb + PABYTES + tid * GROWB;

    auto copy_chunk = [&](int c, int stg) {
        const uint32_t off = (uint32_t)stg * PSTAGE;
        const int k0 = c * 64;
#pragma unroll
        for (int j = 0; j < 4; ++j)
            CP16(adst0 + off + 16 * j, asrc0 + k0 + 8 * j);
#pragma unroll
        for (int j = 0; j < 8; ++j)
            CP16(bdst0 + off + 16 * j, bsrc0 + k0 + 8 * j);
    };

    copy_chunk(0, 0); CP_COMMIT();
    copy_chunk(1, 1); CP_COMMIT();

    uint32_t af[4][4];             // single-buffered A fragments (16 regs)
    uint32_t bf[2][4];             // B fragments, one 32-col half (8 regs)

    int buf = 0;
    for (int c = 0; c < 16; ++c) {
        if (c < 15) CP_WAIT1(); else CP_WAIT0();
        __syncthreads();
        if (c < 14) {
            int nb = buf + 2; if (nb >= 3) nb -= 3;
            copy_chunk(c + 2, nb);
            CP_COMMIT();
        }

        const uint32_t af_b = a_frag0 + (uint32_t)buf * PSTAGE;
        const uint32_t bf_b = b_frag0 + (uint32_t)buf * PSTAGE;

#pragma unroll
        for (int ks = 0; ks < 4; ++ks) {
            // A fragments for this ks
#pragma unroll
            for (int mt = 0; mt < 4; ++mt)
                LDSM_X4(af[mt][0], af[mt][1], af[mt][2], af[mt][3],
                        af_b + (uint32_t)(mt * 16 * GROWB + ks * 32));
            // B half 0 (rows +0, +16)
#pragma unroll
            for (int nb2 = 0; nb2 < 2; ++nb2)
                LDSM_X4(bf[nb2][0], bf[nb2][1], bf[nb2][2], bf[nb2][3],
                        bf_b + (uint32_t)(nb2 * 16 * GROWB + ks * 32));
#pragma unroll
            for (int mt = 0; mt < 4; ++mt)
#pragma unroll
                for (int nt = 0; nt < 4; ++nt)
                    mma_f16(acc[mt][nt], af[mt],
                            bf[nt >> 1][(nt & 1) * 2],
                            bf[nt >> 1][(nt & 1) * 2 + 1]);
            // B half 1 (rows +32, +48) — WAR reuse after half-0 MMAs
#pragma unroll
            for (int nb2 = 0; nb2 < 2; ++nb2)
                LDSM_X4(bf[nb2][0], bf[nb2][1], bf[nb2][2], bf[nb2][3],
                        bf_b + (uint32_t)((32 + nb2 * 16) * GROWB + ks * 32));
#pragma unroll
            for (int mt = 0; mt < 4; ++mt)
#pragma unroll
                for (int nt = 0; nt < 4; ++nt)
                    mma_f16(acc[mt][4 + nt], af[mt],
                            bf[nt >> 1][(nt & 1) * 2],
                            bf[nt >> 1][(nt & 1) * 2 + 1]);
        }
        if (++buf == 3) buf = 0;
    }

    // epilogue: +bias, f32 out
    const int r_base = m0 + warp_m * 64 + (lane >> 2);
    const int c_base = n0 + warp_n * 64 + (lane & 3) * 2;
#pragma unroll
    for (int mt = 0; mt < 4; ++mt) {
#pragma unroll
        for (int j = 0; j < 8; ++j) {
            const int row = r_base + mt * 16;
            const int colg = c_base + (j >> 2) * 32 + (j & 3) * 8;
            float2 lo = make_float2(acc[mt][j][0] + bp[colg],
                                    acc[mt][j][1] + bp[colg + 1]);
            float2 hi = make_float2(acc[mt][j][2] + bp[colg],
                                    acc[mt][j][3] + bp[colg + 1]);
            *(float2*)(out + (size_t)row * Ee + colg) = lo;
            *(float2*)(out + (size_t)(row + 8) * Ee + colg) = hi;
        }
    }
}

// ---------------------------------------------------------------------------
// fp16 causal flash attention (R14-proven): KV tile 64, 3-stage ring,
// 2 CTAs/SM, reversed qi scheduling. grid = (8, 128), block 256.
// ---------------------------------------------------------------------------
#define APITCH 72
#define AROWB (APITCH*2)                  // 144 bytes
#define AQ_BYTES (128*AROWB)              // 18432
#define AK_BYTES (64*AROWB)               // 9216
#define AKV_STAGE (2*AK_BYTES)            // 18432 (K+V)
#define ASMEM_BYTES (AQ_BYTES + 3*AKV_STAGE)  // 73728

__global__ __launch_bounds__(256, 2) void attn_mma_kernel()
{
    extern __shared__ uint32_t dsm[];
    const uint32_t sb = smem_u32(dsm);

    const int tid = threadIdx.x;
    const int lane = tid & 31;
    const int wid = tid >> 5;
    const int qi = (int)gridDim.x - 1 - (int)blockIdx.x;
    const int bh = blockIdx.y;
    const int qm0 = qi * 128;
    const size_t base = (size_t)bh * (Tt * Dh);
    const float scale = 0.125f;

    {
        const int r = tid >> 1, ccol = (tid & 1) * 32;
        const __half* qp = g_Qh + base + (size_t)(qm0 + r) * Dh + ccol;
        const uint32_t dst = sb + r * AROWB + ccol * 2;
#pragma unroll
        for (int j = 0; j < 4; ++j) CP16(dst + 16 * j, qp + 8 * j);
    }
    const int kv_row = tid >> 2;
    const int kv_q = tid & 3;
    auto copy_kv = [&](int kt, int buf) {
        const int kv0 = kt * 64;
        const uint32_t kb = sb + AQ_BYTES + (uint32_t)buf * AKV_STAGE;
        const __half* kp = g_Kh + base + (size_t)(kv0 + kv_row) * Dh + kv_q * 16;
        const __half* vp = g_Vh + base + (size_t)(kv0 + kv_row) * Dh + kv_q * 16;
        const uint32_t dst = kb + kv_row * AROWB + kv_q * 32;
        CP16(dst, kp);           CP16(dst + 16, kp + 8);
        CP16(dst + AK_BYTES, vp); CP16(dst + AK_BYTES + 16, vp + 8);
    };
    const int ntile = 2 * (qi + 1);
    copy_kv(0, 0); CP_COMMIT();
    copy_kv(1, 1); CP_COMMIT();

    float m0r = -1e30f, m1r = -1e30f, l0r = 0.0f, l1r = 0.0f;
    float accO[8][4] = {};

    const uint32_t aq_frag = sb +
        (wid * 16 + (lane & 15)) * AROWB + (lane >> 4) * 16;
    const uint32_t bk_off =
        ((lane & 7) + ((lane >> 4) << 3)) * AROWB + ((lane >> 3) & 1) * 16;
    const uint32_t bv_off =
        ((lane & 7) + (((lane >> 3) & 1) << 3)) * AROWB + (lane >> 4) * 16;

    const int row0 = qm0 + wid * 16 + (lane >> 2);

    for (int kt = 0; kt < ntile; ++kt) {
        if (kt < ntile - 1) CP_WAIT1(); else CP_WAIT0();
        __syncthreads();
        if (kt + 2 < ntile) {
            int nb = kt + 2; int stg = nb % 3;
            copy_kv(nb, stg); CP_COMMIT();
        }

        const uint32_t kbase = sb + AQ_BYTES + (uint32_t)(kt % 3) * AKV_STAGE;
        const uint32_t vbase = kbase + AK_BYTES;
        const int kv0 = kt * 64;

        float s[8][4];
#pragma unroll
        for (int i = 0; i < 8; ++i)
#pragma unroll
            for (int j = 0; j < 4; ++j) s[i][j] = 0.0f;

#pragma unroll
        for (int ks = 0; ks < 4; ++ks) {
            uint32_t aq[4];
            LDSM_X4(aq[0], aq[1], aq[2], aq[3], aq_frag + ks * 32);
#pragma unroll
            for (int nb = 0; nb < 4; ++nb) {
                uint32_t bk[4];
                LDSM_X4(bk[0], bk[1], bk[2], bk[3],
                        kbase + bk_off + (uint32_t)nb * (16 * AROWB) + ks * 32);
                mma_f16(s[2 * nb],     aq, bk[0], bk[1]);
                mma_f16(s[2 * nb + 1], aq, bk[2], bk[3]);
            }
        }

        if (kt >= 2 * qi) {
#pragma unroll
            for (int nt = 0; nt < 8; ++nt) {
                const int col = kv0 + nt * 8 + (lane & 3) * 2;
                s[nt][0] = (col     <= row0)     ? s[nt][0] * scale : -1e30f;
                s[nt][1] = (col + 1 <= row0)     ? s[nt][1] * scale : -1e30f;
                s[nt][2] = (col     <= row0 + 8) ? s[nt][2] * scale : -1e30f;
                s[nt][3] = (col + 1 <= row0 + 8) ? s[nt][3] * scale : -1e30f;
            }
        } else {
#pragma unroll
            for (int nt = 0; nt < 8; ++nt) {
                s[nt][0] *= scale; s[nt][1] *= scale;
                s[nt][2] *= scale; s[nt][3] *= scale;
            }
        }

        float mx0 = -1e30f, mx1 = -1e30f;
#pragma unroll
        for (int nt = 0; nt < 8; ++nt) {
            mx0 = fmaxf(mx0, fmaxf(s[nt][0], s[nt][1]));
            mx1 = fmaxf(mx1, fmaxf(s[nt][2], s[nt][3]));
        }
        mx0 = fmaxf(mx0, __shfl_xor_sync(0xffffffffu, mx0, 1));
        mx0 = fmaxf(mx0, __shfl_xor_sync(0xffffffffu, mx0, 2));
        mx1 = fmaxf(mx1, __shfl_xor_sync(0xffffffffu, mx1, 1));
        mx1 = fmaxf(mx1, __shfl_xor_sync(0xffffffffu, mx1, 2));

        const float mn0 = fmaxf(m0r, mx0), mn1 = fmaxf(m1r, mx1);
        const float cr0 = __expf(m0r - mn0), cr1 = __expf(m1r - mn1);
        m0r = mn0; m1r = mn1;

        uint32_t ph[8][2];
        float sm0 = 0.0f, sm1 = 0.0f;
#pragma unroll
        for (int nt = 0; nt < 8; ++nt) {
            float p00 = __expf(s[nt][0] - mn0);
            float p01 = __expf(s[nt][1] - mn0);
            float p10 = __expf(s[nt][2] - mn1);
            float p11 = __expf(s[nt][3] - mn1);
            sm0 += p00 + p01; sm1 += p10 + p11;
            ph[nt][0] = h2u(__floats2half2_rn(p00, p01));
            ph[nt][1] = h2u(__floats2half2_rn(p10, p11));
        }
        sm0 += __shfl_xor_sync(0xffffffffu, sm0, 1);
        sm0 += __shfl_xor_sync(0xffffffffu, sm0, 2);
        sm1 += __shfl_xor_sync(0xffffffffu, sm1, 1);
        sm1 += __shfl_xor_sync(0xffffffffu, sm1, 2);
        l0r = l0r * cr0 + sm0;
        l1r = l1r * cr1 + sm1;

#pragma unroll
        for (int dt = 0; dt < 8; ++dt) {
            accO[dt][0] *= cr0; accO[dt][1] *= cr0;
            accO[dt][2] *= cr1; accO[dt][3] *= cr1;
        }

#pragma unroll
        for (int j = 0; j < 4; ++j) {
            uint32_t a[4] = { ph[2 * j][0], ph[2 * j][1],
                              ph[2 * j + 1][0], ph[2 * j + 1][1] };
#pragma unroll
            for (int dt = 0; dt < 4; ++dt) {
                uint32_t bv[4];
                LDSM_X4_T(bv[0], bv[1], bv[2], bv[3],
                          vbase + bv_off + (uint32_t)j * (16 * AROWB) + dt * 32);
                mma_f16(accO[2 * dt],     a, bv[0], bv[1]);
                mma_f16(accO[2 * dt + 1], a, bv[2], bv[3]);
            }
        }
        __syncthreads();
    }

    const float inv0 = 1.0f / l0r, inv1 = 1.0f / l1r;
    const int b = bh >> 4, h = bh & 15;
    const int t0 = row0;
#pragma unroll
    for (int dt = 0; dt < 8; ++dt) {
        const int d = dt * 8 + (lane & 3) * 2;
        __half2 lo = __floats2half2_rn(accO[dt][0] * inv0, accO[dt][1] * inv0);
        __half2 hi = __floats2half2_rn(accO[dt][2] * inv1, accO[dt][3] * inv1);
        *(__half2*)(g_Hid + ((size_t)b * Tt + t0) * Ee + h * Dh + d) = lo;
        *(__half2*)(g_Hid + ((size_t)b * Tt + t0 + 8) * Ee + h * Dh + d) = hi;
    }
}

// ---------------------------------------------------------------------------
extern "C" void kernel_launch(void* const* d_in, const int* in_sizes, int n_in,
                              void* d_out, int out_size)
{
    const float* x  = (const float*)d_in[0];
    const float* Wq = (const float*)d_in[1];
    const float* Wk = (const float*)d_in[2];
    const float* Wv = (const float*)d_in[3];
    const float* Wp = (const float*)d_in[4];
    const float* bp = (const float*)d_in[5];
    float* out = (float*)d_out;

    cudaFuncSetAttribute(qkv_mma_kernel,
                         cudaFuncAttributeMaxDynamicSharedMemorySize, QKV_SMEM);
    cudaFuncSetAttribute(proj_mma_kernel,
                         cudaFuncAttributeMaxDynamicSharedMemorySize, PROJ_SMEM);
    cudaFuncSetAttribute(attn_mma_kernel,
                         cudaFuncAttributeMaxDynamicSharedMemorySize, ASMEM_BYTES);

    {
        __half* xh;  cudaGetSymbolAddress((void**)&xh,  g_Xh);
        __half* wph; cudaGetSymbolAddress((void**)&wph, g_Wph);
        prep_half_kernel<<<(Mm * Ee) / 1024, 256>>>(x, xh);
        prep_half_kernel<<<(Ee * Ee) / 1024, 256>>>(Wp, wph);
        dim3 gw(Ee / 32, Dh / 32, 3 * Hh);
        prep_wth_kernel<<<gw, 256>>>(Wq, Wk, Wv);
    }
    {
        dim3 grid(3 * Ee / 192, Mm / 128);
        qkv_mma_kernel<<<grid, 384, QKV_SMEM>>>();
    }
    {
        dim3 grid(Tt / 128, Bb * Hh);
        attn_mma_kernel<<<grid, 256, ASMEM_BYTES>>>();
    }
    {
        dim3 grid(Ee / 256, Mm / 128);
        proj_mma_kernel<<<grid, 256, PROJ_SMEM>>>(bp, out);
    }
}

// round 16
// speedup vs baseline: 1.5154x; 1.5154x over previous
#include <cuda_runtime.h>
#include <cuda_fp16.h>
#include <math.h>
#include <stdint.h>

#define Bb 8
#define Tt 1024
#define Ee 1024
#define Hh 16
#define Dh 64
#define Mm (Bb*Tt)   // 8192

// Scratch (allocation-free rule: __device__ globals), all fp16 operands
__device__ __half g_Qh[Bb*Hh*Tt*Dh];
__device__ __half g_Kh[Bb*Hh*Tt*Dh];
__device__ __half g_Vh[Bb*Hh*Tt*Dh];
__device__ __half g_Hid[Mm*Ee];
__device__ __half g_Xh[Mm*Ee];
__device__ __half g_Wth[3*Ee*Ee];    // transposed [3072][1024]
__device__ __half g_Wph[Ee*Ee];      // Wp (already [n][k])

// ============================ helpers ============================
__device__ __forceinline__ uint32_t smem_u32(const void* p) {
    uint32_t a;
    asm("{ .reg .u64 t; cvta.to.shared.u64 t, %1; cvt.u32.u64 %0, t; }"
        : "=r"(a) : "l"(p));
    return a;
}
__device__ __forceinline__ uint32_t h2u(__half2 h) {
    return *reinterpret_cast<uint32_t*>(&h);
}
#define LDSM_X4(r0, r1, r2, r3, addr) \
    asm volatile("ldmatrix.sync.aligned.m8n8.x4.shared.b16 {%0,%1,%2,%3}, [%4];" \
                 : "=r"(r0), "=r"(r1), "=r"(r2), "=r"(r3) : "r"(addr))
#define LDSM_X4_T(r0, r1, r2, r3, addr) \
    asm volatile("ldmatrix.sync.aligned.m8n8.x4.trans.shared.b16 {%0,%1,%2,%3}, [%4];" \
                 : "=r"(r0), "=r"(r1), "=r"(r2), "=r"(r3) : "r"(addr))
#define CP16(dst, src) \
    asm volatile("cp.async.cg.shared.global [%0], [%1], 16;" \
                 :: "r"(dst), "l"(src) : "memory")
#define CP_COMMIT() asm volatile("cp.async.commit_group;" ::: "memory")
#define CP_WAIT1()  asm volatile("cp.async.wait_group 1;" ::: "memory")
#define CP_WAIT0()  asm volatile("cp.async.wait_group 0;" ::: "memory")

__device__ __forceinline__ void mma_f16(float* d, const uint32_t* a,
                                        uint32_t b0, uint32_t b1) {
    asm volatile(
        "mma.sync.aligned.m16n8k16.row.col.f32.f16.f16.f32 "
        "{%0,%1,%2,%3}, {%4,%5,%6,%7}, {%8,%9}, {%0,%1,%2,%3};"
        : "+f"(d[0]), "+f"(d[1]), "+f"(d[2]), "+f"(d[3])
        : "r"(a[0]), "r"(a[1]), "r"(a[2]), "r"(a[3]), "r"(b0), "r"(b1));
}

// ---------------------------------------------------------------------------
// Prep kernels: fp32 -> fp16 conversions
// ---------------------------------------------------------------------------
__global__ __launch_bounds__(256) void prep_half_kernel(
    const float* __restrict__ src, __half* __restrict__ dst)
{
    const size_t i = ((size_t)blockIdx.x * 256 + threadIdx.x) * 4;
    float4 v = *(const float4*)(src + i);
    __half2 h0 = __floats2half2_rn(v.x, v.y);
    __half2 h1 = __floats2half2_rn(v.z, v.w);
    *(uint2*)(dst + i) = make_uint2(h2u(h0), h2u(h1));
}

// W[h][k][d] -> Wth[which*1024 + h*64 + d][k], fp16
__global__ __launch_bounds__(256) void prep_wth_kernel(
    const float* __restrict__ Wq, const float* __restrict__ Wk,
    const float* __restrict__ Wv)
{
    __shared__ float tile[32][33];
    const int which = blockIdx.z >> 4;
    const int h = blockIdx.z & 15;
    const float* Ws = (which == 0) ? Wq : ((which == 1) ? Wk : Wv);
    const int k0 = blockIdx.x * 32;
    const int d0 = blockIdx.y * 32;
    const int tx = threadIdx.x & 31, ty = threadIdx.x >> 5;

#pragma unroll
    for (int j = 0; j < 4; ++j) {
        const int kk = ty + j * 8;
        tile[kk][tx] = Ws[(size_t)h * (Ee * Dh) + (size_t)(k0 + kk) * Dh + d0 + tx];
    }
    __syncthreads();
#pragma unroll
    for (int j = 0; j < 4; ++j) {
        const int dd = ty + j * 8;
        const int n = h * 64 + d0 + dd;
        g_Wth[(size_t)which * (Ee * Ee) + (size_t)n * Ee + k0 + tx] =
            __float2half_rn(tile[tx][dd]);
    }
}

// ---------------------------------------------------------------------------
// NT fp16 GEMM. Warp tile 64x32, K-chunk 64, 4-stage cp.async ring with
// cross-chunk register fragment prefetch (ks0 of chunk c+1 loaded during
// ks3 MMAs of chunk c). qkv: 12 warps (CTA 128x192), proj: 8 warps.
// ---------------------------------------------------------------------------
#define GPITCH 72                         // halves per row
#define GABYTES (128*GPITCH*2)            // 18432

template <int MODE, int WN, int THREADS>
__device__ __forceinline__ void gemm_mma_body(
    const __half* __restrict__ A, const __half* __restrict__ Brows,
    const float* __restrict__ bp, void* __restrict__ outv,
    int m0, int n_outg)
{
    constexpr int BB = WN * 32 * GPITCH * 2;   // B bytes per stage
    constexpr int STAGE = GABYTES + BB;

    extern __shared__ uint32_t dsm[];
    const uint32_t sb = smem_u32(dsm);

    const int tid = threadIdx.x;
    const int lane = tid & 31;
    const int wid = tid >> 5;
    const int warp_m = wid & 1;
    const int warp_n = wid >> 1;          // 0..WN-1

    float acc[4][4][4] = {};

    const uint32_t a_frag0 = sb +
        ((warp_m * 64 + (lane & 15)) * GPITCH + (lane >> 4) * 8) * 2;
    const uint32_t b_frag0 = sb + GABYTES +
        ((warp_n * 32 + (lane & 7) + ((lane >> 4) << 3)) * GPITCH
         + ((lane >> 3) & 1) * 8) * 2;

    const int c_row = tid >> 1;
    const int c_col = (tid & 1) * 32;

    const __half* asrc0 = A + (size_t)(m0 + (c_row & 127)) * Ee + c_col;
    const __half* bsrc0 = Brows + (size_t)c_row * Ee + c_col;
    const uint32_t adst0 = sb + (c_row & 127) * (GPITCH * 2) + c_col * 2;
    const uint32_t bdst0 = sb + GABYTES + c_row * (GPITCH * 2) + c_col * 2;

    auto copy_chunk = [&](int c, int stg) {
        const uint32_t off = (uint32_t)stg * STAGE;
        const int k0 = c * 64;
        if (THREADS == 256 || tid < 256) {
#pragma unroll
            for (int j = 0; j < 4; ++j)
                CP16(adst0 + off + 16 * j, asrc0 + k0 + 8 * j);
        }
#pragma unroll
        for (int j = 0; j < 4; ++j)
            CP16(bdst0 + off + 16 * j, bsrc0 + k0 + 8 * j);
    };

    copy_chunk(0, 0); CP_COMMIT();
    copy_chunk(1, 1); CP_COMMIT();
    copy_chunk(2, 2); CP_COMMIT();

    uint32_t af[2][4][4], bf[2][2][4];

    for (int c = 0; c < 16; ++c) {
        if (c < 14) CP_WAIT1(); else CP_WAIT0();
        __syncthreads();
        if (c < 13) { copy_chunk(c + 3, (c + 3) & 3); CP_COMMIT(); }

        const uint32_t af_b = a_frag0 + (uint32_t)(c & 3) * STAGE;
        const uint32_t bf_b = b_frag0 + (uint32_t)(c & 3) * STAGE;
        const uint32_t af_n = a_frag0 + (uint32_t)((c + 1) & 3) * STAGE;
        const uint32_t bf_n = b_frag0 + (uint32_t)((c + 1) & 3) * STAGE;

        if (c == 0) {   // cold-start preload of chunk0 ks0
#pragma unroll
            for (int mt = 0; mt < 4; ++mt)
                LDSM_X4(af[0][mt][0], af[0][mt][1], af[0][mt][2], af[0][mt][3],
                        af_b + (uint32_t)(mt * 16 * GPITCH * 2));
#pragma unroll
            for (int nb2 = 0; nb2 < 2; ++nb2)
                LDSM_X4(bf[0][nb2][0], bf[0][nb2][1], bf[0][nb2][2], bf[0][nb2][3],
                        bf_b + (uint32_t)(nb2 * 16 * GPITCH * 2));
        }

#pragma unroll
        for (int ks = 0; ks < 4; ++ks) {
            const int cur = ks & 1, nxt = cur ^ 1;
            if (ks < 3) {       // prefetch ks+1 of this chunk
#pragma unroll
                for (int mt = 0; mt < 4; ++mt)
                    LDSM_X4(af[nxt][mt][0], af[nxt][mt][1],
                            af[nxt][mt][2], af[nxt][mt][3],
                            af_b + (uint32_t)(mt * 16 * GPITCH * 2 + (ks + 1) * 32));
#pragma unroll
                for (int nb2 = 0; nb2 < 2; ++nb2)
                    LDSM_X4(bf[nxt][nb2][0], bf[nxt][nb2][1],
                            bf[nxt][nb2][2], bf[nxt][nb2][3],
                            bf_b + (uint32_t)(nb2 * 16 * GPITCH * 2 + (ks + 1) * 32));
            } else if (c < 15) {   // cross-chunk prefetch: ks0 of chunk c+1
#pragma unroll
                for (int mt = 0; mt < 4; ++mt)
                    LDSM_X4(af[nxt][mt][0], af[nxt][mt][1],
                            af[nxt][mt][2], af[nxt][mt][3],
                            af_n + (uint32_t)(mt * 16 * GPITCH * 2));
#pragma unroll
                for (int nb2 = 0; nb2 < 2; ++nb2)
                    LDSM_X4(bf[nxt][nb2][0], bf[nxt][nb2][1],
                            bf[nxt][nb2][2], bf[nxt][nb2][3],
                            bf_n + (uint32_t)(nb2 * 16 * GPITCH * 2));
            }
#pragma unroll
            for (int mt = 0; mt < 4; ++mt)
#pragma unroll
                for (int nt = 0; nt < 4; ++nt)
                    mma_f16(acc[mt][nt], af[cur][mt],
                            bf[cur][nt >> 1][(nt & 1) * 2],
                            bf[cur][nt >> 1][(nt & 1) * 2 + 1]);
        }
    }

    // ---------------- epilogue ----------------
    const int r_base = m0 + warp_m * 64 + (lane >> 2);
    const int c_base = n_outg + warp_n * 32 + (lane & 3) * 2;
#pragma unroll
    for (int mt = 0; mt < 4; ++mt) {
#pragma unroll
        for (int nt = 0; nt < 4; ++nt) {
            const int row = r_base + mt * 16;
            const int colg = c_base + nt * 8;
            if (MODE == 3) {
                float* outp = (float*)outv;
                float2 lo = make_float2(acc[mt][nt][0] + bp[colg],
                                        acc[mt][nt][1] + bp[colg + 1]);
                float2 hi = make_float2(acc[mt][nt][2] + bp[colg],
                                        acc[mt][nt][3] + bp[colg + 1]);
                *(float2*)(outp + (size_t)row * Ee + colg) = lo;
                *(float2*)(outp + (size_t)(row + 8) * Ee + colg) = hi;
            } else {
                const int which = colg >> 10;
                __half* outp = (which == 0) ? g_Qh : ((which == 1) ? g_Kh : g_Vh);
                const int col = colg & 1023;
                const int h = col >> 6, d = col & 63;
                const int b1_ = row >> 10, t1 = row & 1023;
                const int b2_ = (row + 8) >> 10, t2 = (row + 8) & 1023;
                __half2 lo = __floats2half2_rn(acc[mt][nt][0], acc[mt][nt][1]);
                __half2 hi = __floats2half2_rn(acc[mt][nt][2], acc[mt][nt][3]);
                *(__half2*)(outp + (((size_t)(b1_ * Hh + h)) * Tt + t1) * Dh + d) = lo;
                *(__half2*)(outp + (((size_t)(b2_ * Hh + h)) * Tt + t2) * Dh + d) = hi;
            }
        }
    }
}

#define QKV_SMEM (4*(GABYTES + 6*32*GPITCH*2))   // 4*46080 = 184320
#define PROJ_SMEM (4*(GABYTES + 4*32*GPITCH*2))  // 4*36864 = 147456

// merged QKV: 8192 x 3072 x 1024. grid (16, 64), 384 threads (12 warps)
__global__ __launch_bounds__(384, 1) void qkv_mma_kernel()
{
    const int n0g = blockIdx.x * 192;
    gemm_mma_body<0, 6, 384>(g_Xh, g_Wth + (size_t)n0g * Ee, nullptr, nullptr,
                             blockIdx.y * 128, n0g);
}

// proj: 8192 x 1024 x 1024. grid (8, 64), 256 threads (8 warps)
__global__ __launch_bounds__(256, 1) void proj_mma_kernel(
    const float* __restrict__ bp, float* __restrict__ out)
{
    gemm_mma_body<3, 4, 256>(g_Hid, g_Wph + (size_t)blockIdx.x * 128 * Ee, bp,
                             out, blockIdx.y * 128, blockIdx.x * 128);
}

// ---------------------------------------------------------------------------
// fp16 causal flash attention, KV tile 64, 3-stage KV ring, 2 CTAs/SM.
// grid = (8 qtiles REVERSED, B*H=128), block 256.
// ---------------------------------------------------------------------------
#define APITCH 72
#define AROWB (APITCH*2)                  // 144 bytes
#define AQ_BYTES (128*AROWB)              // 18432
#define AK_BYTES (64*AROWB)               // 9216
#define AKV_STAGE (2*AK_BYTES)            // 18432 (K+V)
#define ASMEM_BYTES (AQ_BYTES + 3*AKV_STAGE)  // 73728

__global__ __launch_bounds__(256, 2) void attn_mma_kernel()
{
    extern __shared__ uint32_t dsm[];
    const uint32_t sb = smem_u32(dsm);

    const int tid = threadIdx.x;
    const int lane = tid & 31;
    const int wid = tid >> 5;
    const int qi = (int)gridDim.x - 1 - (int)blockIdx.x;   // heavy blocks first
    const int bh = blockIdx.y;
    const int qm0 = qi * 128;
    const size_t base = (size_t)bh * (Tt * Dh);
    const float scale = 0.125f;

    // Q copy: 128 rows, 2 threads/row
    {
        const int r = tid >> 1, ccol = (tid & 1) * 32;
        const __half* qp = g_Qh + base + (size_t)(qm0 + r) * Dh + ccol;
        const uint32_t dst = sb + r * AROWB + ccol * 2;
#pragma unroll
        for (int j = 0; j < 4; ++j) CP16(dst + 16 * j, qp + 8 * j);
    }
    // KV copy: 64 rows, 4 threads/row, 2 segs K + 2 segs V each
    const int kv_row = tid >> 2;
    const int kv_q = tid & 3;
    auto copy_kv = [&](int kt, int buf) {
        const int kv0 = kt * 64;
        const uint32_t kb = sb + AQ_BYTES + (uint32_t)buf * AKV_STAGE;
        const __half* kp = g_Kh + base + (size_t)(kv0 + kv_row) * Dh + kv_q * 16;
        const __half* vp = g_Vh + base + (size_t)(kv0 + kv_row) * Dh + kv_q * 16;
        const uint32_t dst = kb + kv_row * AROWB + kv_q * 32;
        CP16(dst, kp);           CP16(dst + 16, kp + 8);
        CP16(dst + AK_BYTES, vp); CP16(dst + AK_BYTES + 16, vp + 8);
    };
    const int ntile = 2 * (qi + 1);       // always >= 2
    copy_kv(0, 0); CP_COMMIT();
    copy_kv(1, 1); CP_COMMIT();

    float m0r = -1e30f, m1r = -1e30f, l0r = 0.0f, l1r = 0.0f;
    float accO[8][4] = {};

    const uint32_t aq_frag = sb +
        (wid * 16 + (lane & 15)) * AROWB + (lane >> 4) * 16;
    const uint32_t bk_off =
        ((lane & 7) + ((lane >> 4) << 3)) * AROWB + ((lane >> 3) & 1) * 16;
    const uint32_t bv_off =
        ((lane & 7) + (((lane >> 3) & 1) << 3)) * AROWB + (lane >> 4) * 16;

    const int row0 = qm0 + wid * 16 + (lane >> 2);

    for (int kt = 0; kt < ntile; ++kt) {
        if (kt < ntile - 1) CP_WAIT1(); else CP_WAIT0();
        __syncthreads();
        if (kt + 2 < ntile) {
            int nb = kt + 2; int stg = nb % 3;
            copy_kv(nb, stg); CP_COMMIT();
        }

        const uint32_t kbase = sb + AQ_BYTES + (uint32_t)(kt % 3) * AKV_STAGE;
        const uint32_t vbase = kbase + AK_BYTES;
        const int kv0 = kt * 64;

        // ---- S = Q K^T : 16 q-rows x 64 keys per warp ----
        float s[8][4];
#pragma unroll
        for (int i = 0; i < 8; ++i)
#pragma unroll
            for (int j = 0; j < 4; ++j) s[i][j] = 0.0f;

#pragma unroll
        for (int ks = 0; ks < 4; ++ks) {
            uint32_t aq[4];
            LDSM_X4(aq[0], aq[1], aq[2], aq[3], aq_frag + ks * 32);
#pragma unroll
            for (int nb = 0; nb < 4; ++nb) {
                uint32_t bk[4];
                LDSM_X4(bk[0], bk[1], bk[2], bk[3],
                        kbase + bk_off + (uint32_t)nb * (16 * AROWB) + ks * 32);
                mma_f16(s[2 * nb],     aq, bk[0], bk[1]);
                mma_f16(s[2 * nb + 1], aq, bk[2], bk[3]);
            }
        }

        // ---- mask (last two tiles only) + scale ----
        if (kt >= 2 * qi) {
#pragma unroll
            for (int nt = 0; nt < 8; ++nt) {
                const int col = kv0 + nt * 8 + (lane & 3) * 2;
                s[nt][0] = (col     <= row0)     ? s[nt][0] * scale : -1e30f;
                s[nt][1] = (col + 1 <= row0)     ? s[nt][1] * scale : -1e30f;
                s[nt][2] = (col     <= row0 + 8) ? s[nt][2] * scale : -1e30f;
                s[nt][3] = (col + 1 <= row0 + 8) ? s[nt][3] * scale : -1e30f;
            }
        } else {
#pragma unroll
            for (int nt = 0; nt < 8; ++nt) {
                s[nt][0] *= scale; s[nt][1] *= scale;
                s[nt][2] *= scale; s[nt][3] *= scale;
            }
        }

        // ---- online softmax ----
        float mx0 = -1e30f, mx1 = -1e30f;
#pragma unroll
        for (int nt = 0; nt < 8; ++nt) {
            mx0 = fmaxf(mx0, fmaxf(s[nt][0], s[nt][1]));
            mx1 = fmaxf(mx1, fmaxf(s[nt][2], s[nt][3]));
        }
        mx0 = fmaxf(mx0, __shfl_xor_sync(0xffffffffu, mx0, 1));
        mx0 = fmaxf(mx0, __shfl_xor_sync(0xffffffffu, mx0, 2));
        mx1 = fmaxf(mx1, __shfl_xor_sync(0xffffffffu, mx1, 1));
        mx1 = fmaxf(mx1, __shfl_xor_sync(0xffffffffu, mx1, 2));

        const float mn0 = fmaxf(m0r, mx0), mn1 = fmaxf(m1r, mx1);
        const float cr0 = __expf(m0r - mn0), cr1 = __expf(m1r - mn1);
        m0r = mn0; m1r = mn1;

        uint32_t ph[8][2];
        float sm0 = 0.0f, sm1 = 0.0f;
#pragma unroll
        for (int nt = 0; nt < 8; ++nt) {
            float p00 = __expf(s[nt][0] - mn0);
            float p01 = __expf(s[nt][1] - mn0);
            float p10 = __expf(s[nt][2] - mn1);
            float p11 = __expf(s[nt][3] - mn1);
            sm0 += p00 + p01; sm1 += p10 + p11;
            ph[nt][0] = h2u(__floats2half2_rn(p00, p01));
            ph[nt][1] = h2u(__floats2half2_rn(p10, p11));
        }
        sm0 += __shfl_xor_sync(0xffffffffu, sm0, 1);
        sm0 += __shfl_xor_sync(0xffffffffu, sm0, 2);
        sm1 += __shfl_xor_sync(0xffffffffu, sm1, 1);
        sm1 += __shfl_xor_sync(0xffffffffu, sm1, 2);
        l0r = l0r * cr0 + sm0;
        l1r = l1r * cr1 + sm1;

#pragma unroll
        for (int dt = 0; dt < 8; ++dt) {
            accO[dt][0] *= cr0; accO[dt][1] *= cr0;
            accO[dt][2] *= cr1; accO[dt][3] *= cr1;
        }

        // ---- O += P V : 4 key-slices x (4 V-ldsm.trans + 8 mma) ----
#pragma unroll
        for (int j = 0; j < 4; ++j) {
            uint32_t a[4] = { ph[2 * j][0], ph[2 * j][1],
                              ph[2 * j + 1][0], ph[2 * j + 1][1] };
#pragma unroll
            for (int dt = 0; dt < 4; ++dt) {
                uint32_t bv[4];
                LDSM_X4_T(bv[0], bv[1], bv[2], bv[3],
                          vbase + bv_off + (uint32_t)j * (16 * AROWB) + dt * 32);
                mma_f16(accO[2 * dt],     a, bv[0], bv[1]);
                mma_f16(accO[2 * dt + 1], a, bv[2], bv[3]);
            }
        }
        __syncthreads();
    }

    // ---- normalize + write g_Hid (half) [B, T, H*DH] ----
    const float inv0 = 1.0f / l0r, inv1 = 1.0f / l1r;
    const int b = bh >> 4, h = bh & 15;
    const int t0 = row0;
#pragma unroll
    for (int dt = 0; dt < 8; ++dt) {
        const int d = dt * 8 + (lane & 3) * 2;
        __half2 lo = __floats2half2_rn(accO[dt][0] * inv0, accO[dt][1] * inv0);
        __half2 hi = __floats2half2_rn(accO[dt][2] * inv1, accO[dt][3] * inv1);
        *(__half2*)(g_Hid + ((size_t)b * Tt + t0) * Ee + h * Dh + d) = lo;
        *(__half2*)(g_Hid + ((size_t)b * Tt + t0 + 8) * Ee + h * Dh + d) = hi;
    }
}

// ---------------------------------------------------------------------------
extern "C" void kernel_launch(void* const* d_in, const int* in_sizes, int n_in,
                              void* d_out, int out_size)
{
    const float* x  = (const float*)d_in[0];
    const float* Wq = (const float*)d_in[1];
    const float* Wk = (const float*)d_in[2];
    const float* Wv = (const float*)d_in[3];
    const float* Wp = (const float*)d_in[4];
    const float* bp = (const float*)d_in[5];
    float* out = (float*)d_out;

    cudaFuncSetAttribute(qkv_mma_kernel,
                         cudaFuncAttributeMaxDynamicSharedMemorySize, QKV_SMEM);
    cudaFuncSetAttribute(proj_mma_kernel,
                         cudaFuncAttributeMaxDynamicSharedMemorySize, PROJ_SMEM);
    cudaFuncSetAttribute(attn_mma_kernel,
                         cudaFuncAttributeMaxDynamicSharedMemorySize, ASMEM_BYTES);

    {
        __half* xh;  cudaGetSymbolAddress((void**)&xh,  g_Xh);
        __half* wph; cudaGetSymbolAddress((void**)&wph, g_Wph);
        prep_half_kernel<<<(Mm * Ee) / 1024, 256>>>(x, xh);
        prep_half_kernel<<<(Ee * Ee) / 1024, 256>>>(Wp, wph);
        dim3 gw(Ee / 32, Dh / 32, 3 * Hh);
        prep_wth_kernel<<<gw, 256>>>(Wq, Wk, Wv);
    }
    {
        dim3 grid(3 * Ee / 192, Mm / 128);
        qkv_mma_kernel<<<grid, 384, QKV_SMEM>>>();
    }
    {
        dim3 grid(Tt / 128, Bb * Hh);
        attn_mma_kernel<<<grid, 256, ASMEM_BYTES>>>();
    }
    {
        dim3 grid(Ee / 128, Mm / 128);
        proj_mma_kernel<<<grid, 256, PROJ_SMEM>>>(bp, out);
    }
}